// round 17
// baseline (speedup 1.0000x reference)
#include <cuda_runtime.h>
#include <cuda_fp16.h>
#include <math_constants.h>
#include <cstdint>

#define B_  8
#define LQ_ 2048
#define LK_ 2048
#define D_  128
#define E_  64

// Projected q/k as fp16 hi/lo, v as single fp16. Row-major [B*L][64].
#define PROJ_ELEMS (B_ * LQ_ * E_)
__device__ __align__(16) unsigned char g_qh[PROJ_ELEMS * 2];
__device__ __align__(16) unsigned char g_ql[PROJ_ELEMS * 2];
__device__ __align__(16) unsigned char g_kh[PROJ_ELEMS * 2];
__device__ __align__(16) unsigned char g_kl[PROJ_ELEMS * 2];
__device__ __align__(16) unsigned char g_vh[PROJ_ELEMS * 2];

// ============================ helpers ======================================
__device__ __forceinline__ uint32_t smem_u32(const void* p) {
    uint32_t a;
    asm("{ .reg .u64 t; cvta.to.shared.u64 t, %1; cvt.u32.u64 %0, t; }"
        : "=r"(a) : "l"(p));
    return a;
}
__device__ __forceinline__ unsigned pk2h(float a, float b) {
    __half2 h = __floats2half2_rn(a, b);
    return *reinterpret_cast<unsigned*>(&h);
}
__device__ __forceinline__ float f16_hi(float v) {
    return __half2float(__float2half_rn(v));
}

// D += A * B, m16n8k16, fp16 x fp16 -> f32
__device__ __forceinline__ void mma16816(float* d, const uint32_t* a,
                                         const uint32_t* b)
{
    asm volatile(
        "mma.sync.aligned.m16n8k16.row.col.f32.f16.f16.f32 "
        "{%0,%1,%2,%3}, {%4,%5,%6,%7}, {%8,%9}, {%0,%1,%2,%3};"
        : "+f"(d[0]), "+f"(d[1]), "+f"(d[2]), "+f"(d[3])
        : "r"(a[0]), "r"(a[1]), "r"(a[2]), "r"(a[3]), "r"(b[0]), "r"(b[1]));
}
__device__ __forceinline__ void ldsm4(uint32_t* r, uint32_t addr) {
    asm volatile("ldmatrix.sync.aligned.m8n8.x4.shared.b16 {%0,%1,%2,%3}, [%4];"
        : "=r"(r[0]), "=r"(r[1]), "=r"(r[2]), "=r"(r[3]) : "r"(addr));
}
__device__ __forceinline__ void ldsm4t(uint32_t* r, uint32_t addr) {
    asm volatile("ldmatrix.sync.aligned.m8n8.x4.trans.shared.b16 {%0,%1,%2,%3}, [%4];"
        : "=r"(r[0]), "=r"(r[1]), "=r"(r[2]), "=r"(r[3]) : "r"(addr));
}

// ===========================================================================
// Projection via 3-pass fp16 HMMA (unchanged from R14/R16 passing kernel).
// ===========================================================================
#define PXH 0
#define PXL 32768
#define PWH 65536
#define PWL 81920
#define PROJ_SMEM_BYTES 98304

__global__ __launch_bounds__(256, 1) void proj_kernel(
    const float* __restrict__ query,
    const float* __restrict__ key,
    const float* __restrict__ Wq,
    const float* __restrict__ Wk,
    const float* __restrict__ Wv)
{
    extern __shared__ __align__(1024) unsigned char dynsm[];
    const uint32_t sb = smem_u32(dynsm);

    const float* X;
    const float* W;
    unsigned char* outh;
    unsigned char* outl;
    const int mat = blockIdx.y;
    if (mat == 0)      { X = query; W = Wq; outh = g_qh; outl = g_ql; }
    else if (mat == 1) { X = key;   W = Wk; outh = g_kh; outl = g_kl; }
    else               { X = key;   W = Wv; outh = g_vh; outl = 0; }

    const int tid = threadIdx.x;
    const int wid = tid >> 5;
    const int lane = tid & 31;
    const int gid = lane >> 2;
    const int tig = lane & 3;
    const int stripe = wid * 16;
    const int row0 = blockIdx.x * 128;

    for (int u = tid; u < 2048; u += 256) {       // (row, ch): 128 x 16
        int row = u >> 4, ch = u & 15;
        const float4* src = (const float4*)(X + (size_t)(row0 + row) * D_ + ch * 8);
        float4 a = src[0], bq = src[1];
        float h0 = f16_hi(a.x), h1 = f16_hi(a.y);
        float h2 = f16_hi(a.z), h3 = f16_hi(a.w);
        float h4 = f16_hi(bq.x), h5 = f16_hi(bq.y);
        float h6 = f16_hi(bq.z), h7 = f16_hi(bq.w);
        uint4 wh = make_uint4(pk2h(h0, h1), pk2h(h2, h3), pk2h(h4, h5), pk2h(h6, h7));
        uint4 wl = make_uint4(pk2h(a.x - h0, a.y - h1), pk2h(a.z - h2, a.w - h3),
                              pk2h(bq.x - h4, bq.y - h5), pk2h(bq.z - h6, bq.w - h7));
        uint32_t off = (uint32_t)(row * 256 + ((ch ^ (row & 7)) << 4));
        *(uint4*)(dynsm + PXH + off) = wh;
        *(uint4*)(dynsm + PXL + off) = wl;
    }
    for (int u = tid; u < 1024; u += 256) {       // (n, ch): 64 x 16
        int n = u & 63, ch = u >> 6;
        float v[8];
#pragma unroll
        for (int t = 0; t < 8; t++) v[t] = W[(ch * 8 + t) * 64 + n];
        float h[8];
#pragma unroll
        for (int t = 0; t < 8; t++) h[t] = f16_hi(v[t]);
        uint4 wh = make_uint4(pk2h(h[0], h[1]), pk2h(h[2], h[3]),
                              pk2h(h[4], h[5]), pk2h(h[6], h[7]));
        uint4 wl = make_uint4(pk2h(v[0] - h[0], v[1] - h[1]),
                              pk2h(v[2] - h[2], v[3] - h[3]),
                              pk2h(v[4] - h[4], v[5] - h[5]),
                              pk2h(v[6] - h[6], v[7] - h[7]));
        uint32_t off = (uint32_t)(n * 256 + ((ch ^ (n & 7)) << 4));
        *(uint4*)(dynsm + PWH + off) = wh;
        *(uint4*)(dynsm + PWL + off) = wl;
    }
    __syncthreads();

    float c[8][4];
#pragma unroll
    for (int nt = 0; nt < 8; nt++)
#pragma unroll
        for (int j = 0; j < 4; j++) c[nt][j] = 0.0f;

#pragma unroll
    for (int ks = 0; ks < 8; ks++) {   // k = ks*16 .. +15
        uint32_t axh[4], axl[4];
        {
            int arow = stripe + (lane & 7) + ((lane >> 3) & 1) * 8;
            int achunk = ks * 2 + (lane >> 4);
            uint32_t aoff = (uint32_t)(arow * 256 + ((achunk ^ (arow & 7)) << 4));
            ldsm4(axh, sb + PXH + aoff);
            ldsm4(axl, sb + PXL + aoff);
        }
        const int brow7 = lane & 7;
        const int bchunk = ks * 2 + ((lane >> 3) & 1);
        const int bsel = lane >> 4;
        uint32_t bf[8][2];
        uint32_t boffs[4];
#pragma unroll
        for (int np = 0; np < 4; np++) {
            int n = (np * 2 + bsel) * 8 + brow7;
            boffs[np] = (uint32_t)(n * 256 + ((bchunk ^ (n & 7)) << 4));
            uint32_t t[4];
            ldsm4(t, sb + PWH + boffs[np]);
            bf[np * 2][0] = t[0]; bf[np * 2][1] = t[1];
            bf[np * 2 + 1][0] = t[2]; bf[np * 2 + 1][1] = t[3];
        }
#pragma unroll
        for (int nt = 0; nt < 8; nt++) mma16816(c[nt], axh, bf[nt]);
#pragma unroll
        for (int nt = 0; nt < 8; nt++) mma16816(c[nt], axl, bf[nt]);
#pragma unroll
        for (int np = 0; np < 4; np++) {
            uint32_t t[4];
            ldsm4(t, sb + PWL + boffs[np]);
            bf[np * 2][0] = t[0]; bf[np * 2][1] = t[1];
            bf[np * 2 + 1][0] = t[2]; bf[np * 2 + 1][1] = t[3];
        }
#pragma unroll
        for (int nt = 0; nt < 8; nt++) mma16816(c[nt], axh, bf[nt]);
    }

    {
        int r0 = row0 + stripe + gid;
        int r1 = r0 + 8;
#pragma unroll
        for (int nt = 0; nt < 8; nt++) {
            int col = nt * 8 + 2 * tig;
            float h0 = f16_hi(c[nt][0]), h1 = f16_hi(c[nt][1]);
            float h2 = f16_hi(c[nt][2]), h3 = f16_hi(c[nt][3]);
            size_t o0 = ((size_t)r0 * 64 + col) * 2;
            size_t o1 = ((size_t)r1 * 64 + col) * 2;
            *(unsigned*)(outh + o0) = pk2h(h0, h1);
            *(unsigned*)(outh + o1) = pk2h(h2, h3);
            if (outl) {
                *(unsigned*)(outl + o0) = pk2h(c[nt][0] - h0, c[nt][1] - h1);
                *(unsigned*)(outl + o1) = pk2h(c[nt][2] - h2, c[nt][3] - h3);
            }
        }
    }
}

// ===========================================================================
// Flash attention, fp16 HMMA. QK 3-pass hi/lo; PV 1-pass.
// R17: 3-stage cp.async pipeline + software-pipelined loop:
//   softmax(S_t)/pack P_t -> barrier+prefetch(t+2) -> QK(t+1) -> PV(t)
// so QK(t+1) and PV(t) issue back-to-back and the next softmax's c-dependency
// drains behind PV. 3 stages make slot(t+2) != slot(t) (V_t read after the
// barrier).
// grid (16, 8), 512 threads = 16 warps. Warp (rw = wid&7, half = wid>>3):
// 16 q-rows x 64 keys; independent per-half (m,l,O) streams merged in the
// epilogue. Smem tiles [128 rows][64 fp16], XOR-swizzled 16B.
// ===========================================================================
#define SQH 0
#define SQL 16384
#define STAGE0 32768
#define STAGE_STRIDE 49152       // KH +0, KL +16384, VH +32768
#define SREDM (STAGE0 + 3 * STAGE_STRIDE)          // 180224: float[128] m
#define SREDL (SREDM + 512)                        // float[128] l
#define FLASH_SMEM_BYTES (SREDM + 1024)            // 181248
// epilogue scratch sO [128][64] f32 overlays SQH/SQL (32 KB)

__device__ __forceinline__ void prefetch_tile(uint32_t sb, uint32_t stage_base,
                                              size_t gbase, int tid)
{
    const uint4* kh = (const uint4*)(g_kh + gbase);
    const uint4* kl = (const uint4*)(g_kl + gbase);
    const uint4* vh = (const uint4*)(g_vh + gbase);
#pragma unroll
    for (int j = 0; j < 6; j++) {
        int i = tid + j * 512;           // 0..3071
        int region = i >> 10;            // 0=KH 1=KL 2=VH
        int idx = i & 1023;
        int row = idx >> 3, ch = idx & 7;
        int d = row * 8 + (ch ^ (row & 7));
        const uint4* g = (region == 0 ? kh : (region == 1 ? kl : vh)) + idx;
        uint32_t s = sb + stage_base + (uint32_t)region * 16384u + (uint32_t)d * 16u;
        asm volatile("cp.async.cg.shared.global [%0], [%1], 16;"
                     :: "r"(s), "l"(g));
    }
    asm volatile("cp.async.commit_group;" ::: "memory");
}

__global__ __launch_bounds__(512, 1) void flash_kernel(float* __restrict__ out)
{
    extern __shared__ __align__(1024) unsigned char dynsm[];
    const uint32_t sb = smem_u32(dynsm);

    const int tid = threadIdx.x;
    const int wid = tid >> 5;
    const int lane = tid & 31;
    const int gid = lane >> 2;    // row group within 8
    const int tig = lane & 3;     // col pair
    const int rw = wid & 7;
    const int half = wid >> 3;
    const int stripe = rw * 16;   // this warp's q-rows
    const int kbase = half * 64;  // this warp's keys
    const int b = blockIdx.y;
    const int qt = blockIdx.x;
    const int r0 = stripe + gid;
    const int r1 = r0 + 8;

    const size_t kvrow0 = (size_t)b * LK_ * 64 * 2;   // byte base of batch
    const size_t tile_bytes = (size_t)128 * 64 * 2;

    // prefetch tiles 0 and 1 while loading Q
    prefetch_tile(sb, STAGE0, kvrow0, tid);
    prefetch_tile(sb, STAGE0 + STAGE_STRIDE, kvrow0 + tile_bytes, tid);

    // ---- load Q hi/lo tiles into swizzled smem (resident) ---------------
    {
        const size_t base = ((size_t)b * LQ_ + qt * 128) * 64 * 2;  // bytes
        const uint4* gh = (const uint4*)(g_qh + base);
        const uint4* gl = (const uint4*)(g_ql + base);
        uint4* dh = (uint4*)(dynsm + SQH);
        uint4* dl = (uint4*)(dynsm + SQL);
        for (int i = tid; i < 1024; i += 512) {
            int row = i >> 3, ch = i & 7;
            int d = row * 8 + (ch ^ (row & 7));
            dh[d] = gh[i];
            dl[d] = gl[i];
        }
    }

    float o[8][4];
#pragma unroll
    for (int i = 0; i < 8; i++)
#pragma unroll
        for (int j = 0; j < 4; j++) o[i][j] = 0.0f;
    float mA = -CUDART_INF_F, mB = -CUDART_INF_F, lA = 0.0f, lB = 0.0f;

    float c[8][4];
    uint32_t pp[4][4];   // packed P for PV (persisted across QK(t+1))

    // A-fragment addresses (loop-invariant)
    const int arow = stripe + (lane & 7) + ((lane >> 3) & 1) * 8;
    const int brow = lane & 7;
    const int bsel = lane >> 4;
    const int vrow_base = kbase + (lane & 15);
    const int vsel = lane >> 4;

    // QK block: c = 3-pass S for stage at sKH (expects c zeroed by caller)
    auto qk_block = [&](uint32_t sKH) {
        const uint32_t sKL = sKH + 16384;
#pragma unroll
        for (int ks = 0; ks < 4; ks++) {
            uint32_t aqh[4], aql[4];
            {
                int achunk = ks * 2 + (lane >> 4);
                uint32_t aoff = (uint32_t)(arow * 128 +
                                ((achunk ^ (arow & 7)) << 4));
                ldsm4(aqh, sb + SQH + aoff);
                ldsm4(aql, sb + SQL + aoff);
            }
            const int bchunk = ks * 2 + ((lane >> 3) & 1);
            uint32_t bf[8][2];
            uint32_t boffs[4];
#pragma unroll
            for (int np = 0; np < 4; np++) {
                int row = kbase + (np * 2 + bsel) * 8 + brow;
                boffs[np] = (uint32_t)(row * 128 + ((bchunk ^ (row & 7)) << 4));
                uint32_t t[4];
                ldsm4(t, sb + sKH + boffs[np]);
                bf[np * 2][0] = t[0]; bf[np * 2][1] = t[1];
                bf[np * 2 + 1][0] = t[2]; bf[np * 2 + 1][1] = t[3];
            }
#pragma unroll
            for (int nt = 0; nt < 8; nt++) mma16816(c[nt], aqh, bf[nt]);
#pragma unroll
            for (int nt = 0; nt < 8; nt++) mma16816(c[nt], aql, bf[nt]);
#pragma unroll
            for (int np = 0; np < 4; np++) {
                uint32_t t[4];
                ldsm4(t, sb + sKL + boffs[np]);
                bf[np * 2][0] = t[0]; bf[np * 2][1] = t[1];
                bf[np * 2 + 1][0] = t[2]; bf[np * 2 + 1][1] = t[3];
            }
#pragma unroll
            for (int nt = 0; nt < 8; nt++) mma16816(c[nt], aqh, bf[nt]);
        }
    };

    // ---- preamble: S_0 ---------------------------------------------------
    asm volatile("cp.async.wait_group 0;" ::: "memory");
    __syncthreads();
#pragma unroll
    for (int nt = 0; nt < 8; nt++)
#pragma unroll
        for (int j = 0; j < 4; j++) c[nt][j] = 0.0f;
    qk_block(STAGE0);   // slot 0 = tile 0

    for (int t = 0; t < 16; t++) {
        // ---- softmax on c = S_t; pack P_t; rescale o --------------------
        float mx0 = -CUDART_INF_F, mx1 = -CUDART_INF_F;
#pragma unroll
        for (int nt = 0; nt < 8; nt++) {
            mx0 = fmaxf(mx0, fmaxf(c[nt][0], c[nt][1]));
            mx1 = fmaxf(mx1, fmaxf(c[nt][2], c[nt][3]));
        }
        mx0 = fmaxf(mx0, __shfl_xor_sync(0xffffffffu, mx0, 1));
        mx0 = fmaxf(mx0, __shfl_xor_sync(0xffffffffu, mx0, 2));
        mx1 = fmaxf(mx1, __shfl_xor_sync(0xffffffffu, mx1, 1));
        mx1 = fmaxf(mx1, __shfl_xor_sync(0xffffffffu, mx1, 2));

        float nmA = fmaxf(mA, mx0), nmB = fmaxf(mB, mx1);
        float corrA = __expf(mA - nmA), corrB = __expf(mB - nmB);
        mA = nmA; mB = nmB;

        float s0 = 0.0f, s1 = 0.0f;
#pragma unroll
        for (int nt = 0; nt < 8; nt++) {
            c[nt][0] = __expf(c[nt][0] - mA);
            c[nt][1] = __expf(c[nt][1] - mA);
            c[nt][2] = __expf(c[nt][2] - mB);
            c[nt][3] = __expf(c[nt][3] - mB);
            s0 += c[nt][0] + c[nt][1];
            s1 += c[nt][2] + c[nt][3];
        }
        s0 += __shfl_xor_sync(0xffffffffu, s0, 1);
        s0 += __shfl_xor_sync(0xffffffffu, s0, 2);
        s1 += __shfl_xor_sync(0xffffffffu, s1, 1);
        s1 += __shfl_xor_sync(0xffffffffu, s1, 2);
        lA = lA * corrA + s0;
        lB = lB * corrB + s1;

#pragma unroll
        for (int ks = 0; ks < 4; ks++) {
            pp[ks][0] = pk2h(c[2 * ks][0], c[2 * ks][1]);
            pp[ks][1] = pk2h(c[2 * ks][2], c[2 * ks][3]);
            pp[ks][2] = pk2h(c[2 * ks + 1][0], c[2 * ks + 1][1]);
            pp[ks][3] = pk2h(c[2 * ks + 1][2], c[2 * ks + 1][3]);
        }
#pragma unroll
        for (int nt = 0; nt < 8; nt++) {
            o[nt][0] *= corrA; o[nt][1] *= corrA;
            o[nt][2] *= corrB; o[nt][3] *= corrB;
        }

        // ---- stage sync: tile t+1 ready; slot(t+2) safe to overwrite ----
        asm volatile("cp.async.wait_group 0;" ::: "memory");
        __syncthreads();
        if (t + 2 < 16)
            prefetch_tile(sb, STAGE0 + (uint32_t)((t + 2) % 3) * STAGE_STRIDE,
                          kvrow0 + (size_t)(t + 2) * tile_bytes, tid);

        // ---- QK(t+1) into c (independent of o, P_t) ---------------------
        if (t + 1 < 16) {
#pragma unroll
            for (int nt = 0; nt < 8; nt++)
#pragma unroll
                for (int j = 0; j < 4; j++) c[nt][j] = 0.0f;
            qk_block(STAGE0 + (uint32_t)((t + 1) % 3) * STAGE_STRIDE);
        }

        // ---- PV(t): o += P_t V_t ----------------------------------------
        {
            const uint32_t sVH = STAGE0 + (uint32_t)(t % 3) * STAGE_STRIDE + 32768u;
#pragma unroll
            for (int ks = 0; ks < 4; ks++) {
                const int vrow = vrow_base + ks * 16;
                uint32_t bv[8][2];
#pragma unroll
                for (int np = 0; np < 4; np++) {
                    int chunk = np * 2 + vsel;
                    uint32_t voff = (uint32_t)(vrow * 128 +
                                    ((chunk ^ (vrow & 7)) << 4));
                    uint32_t t4[4];
                    ldsm4t(t4, sb + sVH + voff);
                    bv[np * 2][0] = t4[0]; bv[np * 2][1] = t4[1];
                    bv[np * 2 + 1][0] = t4[2]; bv[np * 2 + 1][1] = t4[3];
                }
#pragma unroll
                for (int nt = 0; nt < 8; nt++) mma16816(o[nt], pp[ks], bv[nt]);
            }
        }
    }

    // ---- epilogue: merge half streams, normalize, write -----------------
    __syncthreads();               // all smem tile reads done; reuse as scratch
    float* sO = (float*)dynsm;     // [128][64] overlays SQH/SQL
    float* sM1 = (float*)(dynsm + SREDM);
    float* sL1 = (float*)(dynsm + SREDL);
    if (half == 1) {
#pragma unroll
        for (int nt = 0; nt < 8; nt++) {
            int e = nt * 8 + 2 * tig;
            *(float2*)(sO + r0 * 64 + e) = make_float2(o[nt][0], o[nt][1]);
            *(float2*)(sO + r1 * 64 + e) = make_float2(o[nt][2], o[nt][3]);
        }
        if (tig == 0) { sM1[r0] = mA; sL1[r0] = lA; sM1[r1] = mB; sL1[r1] = lB; }
    }
    __syncthreads();
    if (half == 0) {
        float m1r0 = sM1[r0], l1r0 = sL1[r0];
        float m1r1 = sM1[r1], l1r1 = sL1[r1];
        float mm0 = fmaxf(mA, m1r0), mm1 = fmaxf(mB, m1r1);
        float a00 = __expf(mA - mm0), a01 = __expf(m1r0 - mm0);
        float a10 = __expf(mB - mm1), a11 = __expf(m1r1 - mm1);
        float inv0 = 1.0f / (lA * a00 + l1r0 * a01);
        float inv1 = 1.0f / (lB * a10 + l1r1 * a11);
        float* op = out + ((size_t)b * LQ_ + qt * 128) * E_;
#pragma unroll
        for (int nt = 0; nt < 8; nt++) {
            int e = nt * 8 + 2 * tig;
            float2 p0 = *(float2*)(sO + r0 * 64 + e);
            float2 p1 = *(float2*)(sO + r1 * 64 + e);
            *(float2*)(op + (size_t)r0 * E_ + e) =
                make_float2((o[nt][0] * a00 + p0.x * a01) * inv0,
                            (o[nt][1] * a00 + p0.y * a01) * inv0);
            *(float2*)(op + (size_t)r1 * E_ + e) =
                make_float2((o[nt][2] * a10 + p1.x * a11) * inv1,
                            (o[nt][3] * a10 + p1.y * a11) * inv1);
        }
    }
}

// ---------------------------------------------------------------------------
extern "C" void kernel_launch(void* const* d_in, const int* in_sizes, int n_in,
                              void* d_out, int out_size)
{
    const float* query = (const float*)d_in[0];
    const float* key   = (const float*)d_in[1];
    const float* Wq    = (const float*)d_in[2];
    const float* Wk    = (const float*)d_in[3];
    const float* Wv    = (const float*)d_in[4];

    cudaFuncSetAttribute(proj_kernel, cudaFuncAttributeMaxDynamicSharedMemorySize,
                         PROJ_SMEM_BYTES);
    cudaFuncSetAttribute(flash_kernel, cudaFuncAttributeMaxDynamicSharedMemorySize,
                         FLASH_SMEM_BYTES);

    dim3 gp(128, 3);
    proj_kernel<<<gp, 256, PROJ_SMEM_BYTES>>>(query, key, Wq, Wk, Wv);

    dim3 gf(LQ_ / 128, B_);
    flash_kernel<<<gf, 512, FLASH_SMEM_BYTES>>>((float*)d_out);
}